// round 12
// baseline (speedup 1.0000x reference)
#include <cuda_runtime.h>
#include <cuda_fp16.h>
#include <cstdint>

// ---------------------------------------------------------------------------
// GAT: N=4096, F_IN=512, HID=64, H=8, alpha=0.2
//  out[n, h*64+d] = elu( softmax_j(leakyrelu(s[h,n]+d[h,j]), mask=adj) @ Wh )
// exp(leakyrelu(s+d)) factorizes -> no per-edge exp.  adj 1% dense -> CSR.
// GEMM: split-fp16 3-term (AhBh + AlBh + AhBl) mma.sync.m16n8k16, cp.async
// double-buffered, M-tile 64 (512 CTAs). Wh stored fp16 (halves attn traffic).
// s/d logits fused into GEMM epilogue from fp32 accumulators.
// ---------------------------------------------------------------------------

#define N_NODES 4096
#define F_IN    512
#define HID     64
#define NHEADS  8
#define NCOLS   512
#define CAP     192

__device__ __half  g_Whh[N_NODES * NCOLS];     // Wh fp16 [N][H*64]
__device__ float4  g_SAB[N_NODES * NHEADS];    // [i*8+h] = (s, e^s, e^.2s, 0)
__device__ float4  g_DJE[N_NODES * NHEADS];
__device__ int     g_deg[N_NODES];
__device__ int     g_nbr[N_NODES * CAP];
__device__ __half  g_xh[N_NODES * F_IN];       // x split hi
__device__ __half  g_xl[N_NODES * F_IN];       // x split lo
__device__ __half  g_Wth[NHEADS * HID * F_IN]; // W^T hi: [h][n][k]
__device__ __half  g_Wtl[NHEADS * HID * F_IN]; // W^T lo

// ---------------------------------------------------------------------------
// Kernel 0a: split x -> (hi, lo) fp16
// ---------------------------------------------------------------------------
__global__ __launch_bounds__(256) void prep_x(const float* __restrict__ x)
{
    size_t base = ((size_t)blockIdx.x * 256 + threadIdx.x) * 8;
    float4 p = *(const float4*)(x + base);
    float4 q = *(const float4*)(x + base + 4);
    float v[8] = {p.x, p.y, p.z, p.w, q.x, q.y, q.z, q.w};
    __align__(16) __half hs[8], ls[8];
#pragma unroll
    for (int j = 0; j < 8; j++) {
        hs[j] = __float2half_rn(v[j]);
        ls[j] = __float2half_rn(v[j] - __half2float(hs[j]));
    }
    *(uint4*)(g_xh + base) = *(uint4*)hs;
    *(uint4*)(g_xl + base) = *(uint4*)ls;
}

// ---------------------------------------------------------------------------
// Kernel 0b: W transpose + split: g_Wt{h,l}[h][n][k] = split(W[h][k][n])
// ---------------------------------------------------------------------------
__global__ __launch_bounds__(256) void prep_w(const float* __restrict__ W)
{
    int b  = blockIdx.x * 256 + threadIdx.x;   // 0..65535
    int k4 = (b & 127) * 4;
    int n  = (b >> 7) & 63;
    int h  = b >> 13;
    const float* src = W + (size_t)h * 32768 + (size_t)k4 * 64 + n;
    float v[4] = {src[0], src[64], src[128], src[192]};
    __align__(8) __half hs[4], ls[4];
#pragma unroll
    for (int j = 0; j < 4; j++) {
        hs[j] = __float2half_rn(v[j]);
        ls[j] = __float2half_rn(v[j] - __half2float(hs[j]));
    }
    size_t o = (size_t)h * 32768 + (size_t)n * 512 + k4;
    *(uint2*)(g_Wth + o) = *(uint2*)hs;
    *(uint2*)(g_Wtl + o) = *(uint2*)ls;
}

// ---------------------------------------------------------------------------
// Kernel 1: adjacency row scan -> CSR (deterministic ascending order)
// ---------------------------------------------------------------------------
__global__ __launch_bounds__(256) void scan_kernel(const float* __restrict__ adj)
{
    __shared__ int wsum[8];
    const int i   = blockIdx.x;
    const int tid = threadIdx.x;
    const int lane = tid & 31, wid = tid >> 5;

    const float4* row = (const float4*)(adj + (size_t)i * N_NODES) + tid * 4;
    unsigned bits = 0;
#pragma unroll
    for (int p = 0; p < 4; p++) {
        float4 v = row[p];
        if (v.x > 0.f) bits |= 1u << (p * 4 + 0);
        if (v.y > 0.f) bits |= 1u << (p * 4 + 1);
        if (v.z > 0.f) bits |= 1u << (p * 4 + 2);
        if (v.w > 0.f) bits |= 1u << (p * 4 + 3);
    }
    int cnt = __popc(bits);
    int incl = cnt;
#pragma unroll
    for (int o = 1; o < 32; o <<= 1) {
        int t = __shfl_up_sync(0xffffffffu, incl, o);
        if (lane >= o) incl += t;
    }
    if (lane == 31) wsum[wid] = incl;
    __syncthreads();
    int wbase = 0;
#pragma unroll
    for (int w = 0; w < 8; w++) if (w < wid) wbase += wsum[w];
    int pos = wbase + incl - cnt;
    if (tid == 0) {
        int t = 0;
#pragma unroll
        for (int w = 0; w < 8; w++) t += wsum[w];
        g_deg[i] = t;
    }
    int base = tid * 16;
    int* dst = g_nbr + (size_t)i * CAP;
    while (bits) {
        int b = __ffs(bits) - 1;
        bits &= bits - 1;
        dst[pos++] = base + b;
    }
}

// ---------------------------------------------------------------------------
// Kernel 2: fp16 3-term GEMM + fused s/d epilogue.
// Block: M=64 x N=64 (one head), BK=32, 256 threads, grid 512.
// 8 warps: wm = warp&1 (2 x m32), wn = warp>>1 (4 x n16).
// Warp tile m32 x n16 = 2 mt x 2 nt.  cp.async double-buffered.
// Smem row stride 40 halfs -> conflict-free frag loads.
// ---------------------------------------------------------------------------
#define NKB   16
#define LDH   40
#define MAT_H (64 * LDH)                  // 2560 halfs per matrix
#define BUF_H (4 * MAT_H)                 // Ah, Al, Bh, Bl
#define DYN_BYTES (2 * BUF_H * 2 + 512 + 2048)

__device__ __forceinline__ uint32_t smem_u32(const void* p) {
    uint32_t a;
    asm("{ .reg .u64 t; cvta.to.shared.u64 t, %1; cvt.u32.u64 %0, t; }"
        : "=r"(a) : "l"(p));
    return a;
}
__device__ __forceinline__ void cp16(uint32_t dst, const void* src) {
    asm volatile("cp.async.ca.shared.global [%0], [%1], 16;"
                 :: "r"(dst), "l"(src) : "memory");
}
__device__ __forceinline__ void mma_f16(float* d, uint32_t a0, uint32_t a1,
                                        uint32_t a2, uint32_t a3,
                                        uint32_t b0, uint32_t b1)
{
    asm volatile(
        "mma.sync.aligned.m16n8k16.row.col.f32.f16.f16.f32 "
        "{%0,%1,%2,%3}, {%4,%5,%6,%7}, {%8,%9}, {%0,%1,%2,%3};"
        : "+f"(d[0]), "+f"(d[1]), "+f"(d[2]), "+f"(d[3])
        : "r"(a0), "r"(a1), "r"(a2), "r"(a3), "r"(b0), "r"(b1));
}

__global__ __launch_bounds__(256) void gemm_f16(const float* __restrict__ a_g)
{
    extern __shared__ __align__(16) char sm[];
    __half* tiles = (__half*)sm;                        // 2 buffers
    float*  a_sm  = (float*)(sm + 2 * BUF_H * 2);       // 128 floats
    float*  sd_sm = (float*)(sm + 2 * BUF_H * 2 + 512); // [64][4][2]

    const int tid  = threadIdx.x;
    const int lane = tid & 31, warp = tid >> 5;
    const int h    = blockIdx.x;
    const int m0   = blockIdx.y * 64;
    const int wm   = warp & 1, wn = warp >> 1;
    const int gid  = lane >> 2, tig = lane & 3;

    const __half* xh  = g_xh + (size_t)m0 * F_IN;
    const __half* xl  = g_xl + (size_t)m0 * F_IN;
    const __half* wth = g_Wth + (size_t)h * 32768;
    const __half* wtl = g_Wtl + (size_t)h * 32768;

    if (tid < 128) a_sm[tid] = a_g[h * 128 + tid];

    const uint32_t tiles_u = smem_u32(tiles);
    const int srow = tid >> 2;          // 0..63
    const int sseg = (tid & 3) * 8;     // 0,8,16,24 (halfs)

    // stage one 32-k block: 4 matrices x 64 rows x 2 x 16B per row
    auto stage = [&](int buf, int k0) {
        uint32_t bu = tiles_u + buf * (BUF_H * 2);
        uint32_t d  = bu + (srow * LDH + sseg) * 2;
        const __half* s0 = xh  + (size_t)srow * F_IN + k0 + sseg;
        const __half* s1 = xl  + (size_t)srow * F_IN + k0 + sseg;
        const __half* s2 = wth + (size_t)srow * F_IN + k0 + sseg;
        const __half* s3 = wtl + (size_t)srow * F_IN + k0 + sseg;
        cp16(d,                 s0);
        cp16(d + MAT_H * 2,     s1);
        cp16(d + 2 * MAT_H * 2, s2);
        cp16(d + 3 * MAT_H * 2, s3);
        asm volatile("cp.async.commit_group;" ::: "memory");
    };

    float acc[2][2][4];
#pragma unroll
    for (int mt = 0; mt < 2; mt++)
#pragma unroll
        for (int nt = 0; nt < 2; nt++)
#pragma unroll
            for (int r = 0; r < 4; r++) acc[mt][nt][r] = 0.f;

    stage(0, 0);

    for (int kb = 0; kb < NKB; kb++) {
        asm volatile("cp.async.wait_group 0;" ::: "memory");
        __syncthreads();
        if (kb + 1 < NKB) stage((kb + 1) & 1, (kb + 1) * 32);

        const __half* Ah = tiles + (kb & 1) * BUF_H;
        const __half* Al = Ah + MAT_H;
        const __half* Bh = Ah + 2 * MAT_H;
        const __half* Bl = Ah + 3 * MAT_H;

#pragma unroll
        for (int c = 0; c < 2; c++) {
            const int kk = c * 16 + 2 * tig;
            uint32_t bh[2][2], bl[2][2];
#pragma unroll
            for (int nt = 0; nt < 2; nt++) {
                const int col = wn * 16 + nt * 8 + gid;
                bh[nt][0] = *(const uint32_t*)(Bh + col * LDH + kk);
                bh[nt][1] = *(const uint32_t*)(Bh + col * LDH + kk + 8);
                bl[nt][0] = *(const uint32_t*)(Bl + col * LDH + kk);
                bl[nt][1] = *(const uint32_t*)(Bl + col * LDH + kk + 8);
            }
#pragma unroll
            for (int mt = 0; mt < 2; mt++) {
                const int r0 = wm * 32 + mt * 16 + gid;
                uint32_t ah0 = *(const uint32_t*)(Ah + r0 * LDH + kk);
                uint32_t ah1 = *(const uint32_t*)(Ah + (r0 + 8) * LDH + kk);
                uint32_t ah2 = *(const uint32_t*)(Ah + r0 * LDH + kk + 8);
                uint32_t ah3 = *(const uint32_t*)(Ah + (r0 + 8) * LDH + kk + 8);
                uint32_t al0 = *(const uint32_t*)(Al + r0 * LDH + kk);
                uint32_t al1 = *(const uint32_t*)(Al + (r0 + 8) * LDH + kk);
                uint32_t al2 = *(const uint32_t*)(Al + r0 * LDH + kk + 8);
                uint32_t al3 = *(const uint32_t*)(Al + (r0 + 8) * LDH + kk + 8);
#pragma unroll
                for (int nt = 0; nt < 2; nt++) {
                    mma_f16(acc[mt][nt], ah0, ah1, ah2, ah3, bh[nt][0], bh[nt][1]);
                    mma_f16(acc[mt][nt], al0, al1, al2, al3, bh[nt][0], bh[nt][1]);
                    mma_f16(acc[mt][nt], ah0, ah1, ah2, ah3, bl[nt][0], bl[nt][1]);
                }
            }
        }
    }

    // ---- epilogue: Wh (fp16) + fused s/d from fp32 acc ----
    float sp[2][2], dp[2][2];
#pragma unroll
    for (int mt = 0; mt < 2; mt++) {
        sp[mt][0] = sp[mt][1] = dp[mt][0] = dp[mt][1] = 0.f;
        const int gr = m0 + wm * 32 + mt * 16 + gid;
#pragma unroll
        for (int nt = 0; nt < 2; nt++) {
            const int coll = wn * 16 + nt * 8 + 2 * tig;   // local col 0..63
            const int col  = h * HID + coll;
            __half2 w01 = __floats2half2_rn(acc[mt][nt][0], acc[mt][nt][1]);
            __half2 w23 = __floats2half2_rn(acc[mt][nt][2], acc[mt][nt][3]);
            *(__half2*)(g_Whh + (size_t)gr * NCOLS + col)       = w01;
            *(__half2*)(g_Whh + (size_t)(gr + 8) * NCOLS + col) = w23;
#pragma unroll
            for (int cc = 0; cc < 2; cc++) {
                float as = a_sm[coll + cc], ad = a_sm[64 + coll + cc];
                sp[mt][0] = fmaf(acc[mt][nt][cc],     as, sp[mt][0]);
                sp[mt][1] = fmaf(acc[mt][nt][2 + cc], as, sp[mt][1]);
                dp[mt][0] = fmaf(acc[mt][nt][cc],     ad, dp[mt][0]);
                dp[mt][1] = fmaf(acc[mt][nt][2 + cc], ad, dp[mt][1]);
            }
        }
    }
#pragma unroll
    for (int o = 1; o < 4; o <<= 1) {
#pragma unroll
        for (int mt = 0; mt < 2; mt++) {
#pragma unroll
            for (int hf = 0; hf < 2; hf++) {
                sp[mt][hf] += __shfl_xor_sync(0xffffffffu, sp[mt][hf], o);
                dp[mt][hf] += __shfl_xor_sync(0xffffffffu, dp[mt][hf], o);
            }
        }
    }
    if (tig == 0) {
#pragma unroll
        for (int mt = 0; mt < 2; mt++)
#pragma unroll
            for (int hf = 0; hf < 2; hf++) {
                int row = wm * 32 + mt * 16 + gid + hf * 8;   // 0..63
                sd_sm[row * 8 + wn * 2 + 0] = sp[mt][hf];
                sd_sm[row * 8 + wn * 2 + 1] = dp[mt][hf];
            }
    }
    __syncthreads();
    if (tid < 64) {
        float s = sd_sm[tid * 8 + 0] + sd_sm[tid * 8 + 2] +
                  sd_sm[tid * 8 + 4] + sd_sm[tid * 8 + 6];
        float d = sd_sm[tid * 8 + 1] + sd_sm[tid * 8 + 3] +
                  sd_sm[tid * 8 + 5] + sd_sm[tid * 8 + 7];
        int gr = m0 + tid;
        g_SAB[gr * 8 + h] = make_float4(s, expf(s), expf(0.2f * s), 0.f);
        g_DJE[gr * 8 + h] = make_float4(d, expf(d), expf(0.2f * d), 0.f);
    }
}

// ---------------------------------------------------------------------------
// Kernel 3: aggregation. 1 block/row, 128 threads, fp16 gathers (8B/thread).
// ---------------------------------------------------------------------------
__global__ __launch_bounds__(128) void attn_kernel(float* __restrict__ out)
{
    __shared__ int    s_list[CAP];
    __shared__ float  s_w[CAP * 8];
    __shared__ float4 s_sab[8];

    const int i   = blockIdx.x;
    const int tid = threadIdx.x;
    const int h   = tid >> 4;

    const int nn = g_deg[i];
    if (tid < 8) s_sab[tid] = g_SAB[i * 8 + tid];
    for (int p = tid; p < nn; p += 128) s_list[p] = g_nbr[(size_t)i * CAP + p];
    __syncthreads();

    for (int idx = tid; idx < nn * 8; idx += 128) {
        int q = idx >> 3, hh = idx & 7;
        int j = s_list[q];
        float4 dje = g_DJE[j * 8 + hh];
        float4 sab = s_sab[hh];
        float t = sab.x + dje.x;
        s_w[idx] = (t > 0.f) ? sab.y * dje.y : sab.z * dje.z;
    }
    __syncthreads();

    const float* wp = s_w + h;
    float4 acc = make_float4(0.f, 0.f, 0.f, 0.f);
    float  den = 0.f;

#pragma unroll 4
    for (int q = 0; q < nn; q++) {
        float w = wp[q * 8];
        int   j = s_list[q];
        uint2 v2 = __ldg((const uint2*)(g_Whh + ((size_t)j << 9)) + tid);
        float2 f0 = __half22float2(*(__half2*)&v2.x);
        float2 f1 = __half22float2(*(__half2*)&v2.y);
        acc.x = fmaf(w, f0.x, acc.x);
        acc.y = fmaf(w, f0.y, acc.y);
        acc.z = fmaf(w, f1.x, acc.z);
        acc.w = fmaf(w, f1.y, acc.w);
        den += w;
    }

    float inv = 1.f / den;
    float4 r = make_float4(acc.x * inv, acc.y * inv, acc.z * inv, acc.w * inv);
    r.x = (r.x > 0.f) ? r.x : (expf(r.x) - 1.f);
    r.y = (r.y > 0.f) ? r.y : (expf(r.y) - 1.f);
    r.z = (r.z > 0.f) ? r.z : (expf(r.z) - 1.f);
    r.w = (r.w > 0.f) ? r.w : (expf(r.w) - 1.f);
    *(float4*)(out + (size_t)i * NCOLS + tid * 4) = r;
}

// ---------------------------------------------------------------------------
extern "C" void kernel_launch(void* const* d_in, const int* in_sizes, int n_in,
                              void* d_out, int out_size)
{
    const float* x   = (const float*)d_in[0];   // [4096, 512]
    const float* adj = (const float*)d_in[1];   // [4096, 4096]
    const float* W   = (const float*)d_in[2];   // [8, 512, 64]
    const float* a   = (const float*)d_in[3];   // [8, 128]
    float* out = (float*)d_out;                 // [4096, 512]

    prep_x<<<1024, 256>>>(x);
    prep_w<<<256, 256>>>(W);
    scan_kernel<<<N_NODES, 256>>>(adj);
    gemm_f16<<<dim3(NHEADS, N_NODES / 64), 256, DYN_BYTES>>>(a);
    attn_kernel<<<N_NODES, 128>>>(out);
}

// round 13
// speedup vs baseline: 1.1920x; 1.1920x over previous
#include <cuda_runtime.h>
#include <cuda_fp16.h>
#include <cstdint>

// ---------------------------------------------------------------------------
// GAT: N=4096, F_IN=512, HID=64, H=8, alpha=0.2
//  out[n, h*64+d] = elu( softmax_j(leakyrelu(s[h,n]+d[h,j]), mask=adj) @ Wh )
// exp(leakyrelu(s+d)) factorizes -> no per-edge exp.  adj 1% dense -> CSR.
// GEMM: split-fp16 2-term (Ah+Al)*Bh, mma.sync.m16n8k16, M-tile 128 (R9 cfg).
// Wh stored fp16 (halves attn gather traffic). s/d fused into GEMM epilogue.
// ---------------------------------------------------------------------------

#define N_NODES 4096
#define F_IN    512
#define HID     64
#define NHEADS  8
#define NCOLS   512
#define CAP     192

__device__ __half  g_Whh[N_NODES * NCOLS];     // Wh fp16 [N][H*64]
__device__ float4  g_SAB[N_NODES * NHEADS];    // [i*8+h] = (s, e^s, e^.2s, 0)
__device__ float4  g_DJE[N_NODES * NHEADS];
__device__ int     g_deg[N_NODES];
__device__ int     g_nbr[N_NODES * CAP];
__device__ __half  g_xh[N_NODES * F_IN];       // x split hi
__device__ __half  g_xl[N_NODES * F_IN];       // x split lo
__device__ __half  g_Wth[NHEADS * HID * F_IN]; // W^T fp16: [h][n][k]

// ---------------------------------------------------------------------------
// Kernel 0a: split x -> (hi, lo) fp16
// ---------------------------------------------------------------------------
__global__ __launch_bounds__(256) void prep_x(const float* __restrict__ x)
{
    size_t base = ((size_t)blockIdx.x * 256 + threadIdx.x) * 8;
    float4 p = *(const float4*)(x + base);
    float4 q = *(const float4*)(x + base + 4);
    float v[8] = {p.x, p.y, p.z, p.w, q.x, q.y, q.z, q.w};
    __align__(16) __half hs[8], ls[8];
#pragma unroll
    for (int j = 0; j < 8; j++) {
        hs[j] = __float2half_rn(v[j]);
        ls[j] = __float2half_rn(v[j] - __half2float(hs[j]));
    }
    *(uint4*)(g_xh + base) = *(uint4*)hs;
    *(uint4*)(g_xl + base) = *(uint4*)ls;
}

// ---------------------------------------------------------------------------
// Kernel 0b: W transpose -> fp16: g_Wth[h][n][k] = fp16(W[h][k][n])
// ---------------------------------------------------------------------------
__global__ __launch_bounds__(256) void prep_w(const float* __restrict__ W)
{
    int b  = blockIdx.x * 256 + threadIdx.x;   // 0..65535
    int k4 = (b & 127) * 4;
    int n  = (b >> 7) & 63;
    int h  = b >> 13;
    const float* src = W + (size_t)h * 32768 + (size_t)k4 * 64 + n;
    __align__(8) __half hs[4];
    hs[0] = __float2half_rn(src[0]);
    hs[1] = __float2half_rn(src[64]);
    hs[2] = __float2half_rn(src[128]);
    hs[3] = __float2half_rn(src[192]);
    *(uint2*)(g_Wth + (size_t)h * 32768 + (size_t)n * 512 + k4) = *(uint2*)hs;
}

// ---------------------------------------------------------------------------
// Kernel 1: adjacency row scan -> CSR (deterministic ascending order)
// ---------------------------------------------------------------------------
__global__ __launch_bounds__(256) void scan_kernel(const float* __restrict__ adj)
{
    __shared__ int wsum[8];
    const int i   = blockIdx.x;
    const int tid = threadIdx.x;
    const int lane = tid & 31, wid = tid >> 5;

    const float4* row = (const float4*)(adj + (size_t)i * N_NODES) + tid * 4;
    unsigned bits = 0;
#pragma unroll
    for (int p = 0; p < 4; p++) {
        float4 v = row[p];
        if (v.x > 0.f) bits |= 1u << (p * 4 + 0);
        if (v.y > 0.f) bits |= 1u << (p * 4 + 1);
        if (v.z > 0.f) bits |= 1u << (p * 4 + 2);
        if (v.w > 0.f) bits |= 1u << (p * 4 + 3);
    }
    int cnt = __popc(bits);
    int incl = cnt;
#pragma unroll
    for (int o = 1; o < 32; o <<= 1) {
        int t = __shfl_up_sync(0xffffffffu, incl, o);
        if (lane >= o) incl += t;
    }
    if (lane == 31) wsum[wid] = incl;
    __syncthreads();
    int wbase = 0;
#pragma unroll
    for (int w = 0; w < 8; w++) if (w < wid) wbase += wsum[w];
    int pos = wbase + incl - cnt;
    if (tid == 0) {
        int t = 0;
#pragma unroll
        for (int w = 0; w < 8; w++) t += wsum[w];
        g_deg[i] = t;
    }
    int base = tid * 16;
    int* dst = g_nbr + (size_t)i * CAP;
    while (bits) {
        int b = __ffs(bits) - 1;
        bits &= bits - 1;
        dst[pos++] = base + b;
    }
}

// ---------------------------------------------------------------------------
// Kernel 2: fp16 2-term GEMM + fused s/d epilogue (R9 configuration).
// Block: M=128 x N=64 (one head), BK=32, 256 threads, grid 256.
// 8 warps: wm = warp>>1 (4 x m32), wn = warp&1 (2 x n32 = 4 x n8).
// cp.async double-buffered.  Smem row stride 40 halfs -> conflict-free.
// ---------------------------------------------------------------------------
#define NKB   16
#define LDH   40
#define A_H   (128 * LDH)                 // 5120 halfs
#define B_H   (64 * LDH)                  // 2560 halfs
#define BUF_H (2 * A_H + B_H)             // 12800 halfs per buffer
#define DYN_BYTES (2 * BUF_H * 2 + 512 + 2048)

__device__ __forceinline__ uint32_t smem_u32(const void* p) {
    uint32_t a;
    asm("{ .reg .u64 t; cvta.to.shared.u64 t, %1; cvt.u32.u64 %0, t; }"
        : "=r"(a) : "l"(p));
    return a;
}
__device__ __forceinline__ void cp16(uint32_t dst, const void* src) {
    asm volatile("cp.async.ca.shared.global [%0], [%1], 16;"
                 :: "r"(dst), "l"(src) : "memory");
}
__device__ __forceinline__ void mma_f16(float* d, uint32_t a0, uint32_t a1,
                                        uint32_t a2, uint32_t a3,
                                        uint32_t b0, uint32_t b1)
{
    asm volatile(
        "mma.sync.aligned.m16n8k16.row.col.f32.f16.f16.f32 "
        "{%0,%1,%2,%3}, {%4,%5,%6,%7}, {%8,%9}, {%0,%1,%2,%3};"
        : "+f"(d[0]), "+f"(d[1]), "+f"(d[2]), "+f"(d[3])
        : "r"(a0), "r"(a1), "r"(a2), "r"(a3), "r"(b0), "r"(b1));
}

__global__ __launch_bounds__(256) void gemm_f16(const float* __restrict__ a_g)
{
    extern __shared__ __align__(16) char sm[];
    __half* tiles = (__half*)sm;                        // 2 buffers
    float*  a_sm  = (float*)(sm + 2 * BUF_H * 2);       // 128 floats
    float*  sd_sm = (float*)(sm + 2 * BUF_H * 2 + 512); // [128][2][2]

    const int tid  = threadIdx.x;
    const int lane = tid & 31, warp = tid >> 5;
    const int h    = blockIdx.x;
    const int m0   = blockIdx.y * 128;
    const int wm   = warp >> 1, wn = warp & 1;
    const int gid  = lane >> 2, tig = lane & 3;

    const __half* xh  = g_xh + (size_t)m0 * F_IN;
    const __half* xl  = g_xl + (size_t)m0 * F_IN;
    const __half* wth = g_Wth + (size_t)h * 32768;

    if (tid < 128) a_sm[tid] = a_g[h * 128 + tid];

    const uint32_t tiles_u = smem_u32(tiles);

    // stage one k-block (id = p*256+tid, p<5): Ah, Al, Bh via 16B cp.async
    auto stage = [&](int buf, int k0) {
        uint32_t bu = tiles_u + buf * (BUF_H * 2);
#pragma unroll
        for (int p = 0; p < 5; p++) {
            int id = tid + p * 256;
            if (id < 512) {                       // A hi
                int r = id >> 2, seg = id & 3;
                cp16(bu + (r * LDH + seg * 8) * 2, xh + (size_t)r * F_IN + k0 + seg * 8);
            } else if (id < 1024) {               // A lo
                int q = id - 512, r = q >> 2, seg = q & 3;
                cp16(bu + (A_H + r * LDH + seg * 8) * 2, xl + (size_t)r * F_IN + k0 + seg * 8);
            } else {                              // B hi
                int q = id - 1024, r = q >> 2, seg = q & 3;
                cp16(bu + (2 * A_H + r * LDH + seg * 8) * 2, wth + (size_t)r * F_IN + k0 + seg * 8);
            }
        }
        asm volatile("cp.async.commit_group;" ::: "memory");
    };

    float acc[2][4][4];
#pragma unroll
    for (int mt = 0; mt < 2; mt++)
#pragma unroll
        for (int nt = 0; nt < 4; nt++)
#pragma unroll
            for (int r = 0; r < 4; r++) acc[mt][nt][r] = 0.f;

    stage(0, 0);

    for (int kb = 0; kb < NKB; kb++) {
        asm volatile("cp.async.wait_group 0;" ::: "memory");
        __syncthreads();
        if (kb + 1 < NKB) stage((kb + 1) & 1, (kb + 1) * 32);

        const __half* Ah = tiles + (kb & 1) * BUF_H;
        const __half* Al = Ah + A_H;
        const __half* Bh = Ah + 2 * A_H;

#pragma unroll
        for (int c = 0; c < 2; c++) {
            const int kb16 = c * 16 + 2 * tig;
            uint32_t bfr[4][2];
#pragma unroll
            for (int nt = 0; nt < 4; nt++) {
                const int col = wn * 32 + nt * 8 + gid;
                bfr[nt][0] = *(const uint32_t*)(Bh + col * LDH + kb16);
                bfr[nt][1] = *(const uint32_t*)(Bh + col * LDH + kb16 + 8);
            }
#pragma unroll
            for (int mt = 0; mt < 2; mt++) {
                const int r0 = wm * 32 + mt * 16 + gid;
                uint32_t ah0 = *(const uint32_t*)(Ah + r0 * LDH + kb16);
                uint32_t ah1 = *(const uint32_t*)(Ah + (r0 + 8) * LDH + kb16);
                uint32_t ah2 = *(const uint32_t*)(Ah + r0 * LDH + kb16 + 8);
                uint32_t ah3 = *(const uint32_t*)(Ah + (r0 + 8) * LDH + kb16 + 8);
                uint32_t al0 = *(const uint32_t*)(Al + r0 * LDH + kb16);
                uint32_t al1 = *(const uint32_t*)(Al + (r0 + 8) * LDH + kb16);
                uint32_t al2 = *(const uint32_t*)(Al + r0 * LDH + kb16 + 8);
                uint32_t al3 = *(const uint32_t*)(Al + (r0 + 8) * LDH + kb16 + 8);
#pragma unroll
                for (int nt = 0; nt < 4; nt++) {
                    mma_f16(acc[mt][nt], ah0, ah1, ah2, ah3, bfr[nt][0], bfr[nt][1]);
                    mma_f16(acc[mt][nt], al0, al1, al2, al3, bfr[nt][0], bfr[nt][1]);
                }
            }
        }
    }

    // ---- epilogue: Wh (fp16) + fused s/d from fp32 accumulators ----
    float sp[2][2], dp[2][2];
#pragma unroll
    for (int mt = 0; mt < 2; mt++) {
        sp[mt][0] = sp[mt][1] = dp[mt][0] = dp[mt][1] = 0.f;
        const int gr = m0 + wm * 32 + mt * 16 + gid;
#pragma unroll
        for (int nt = 0; nt < 4; nt++) {
            const int coll = wn * 32 + nt * 8 + 2 * tig;   // local col 0..63
            const int col  = h * HID + coll;
            *(__half2*)(g_Whh + (size_t)gr * NCOLS + col) =
                __floats2half2_rn(acc[mt][nt][0], acc[mt][nt][1]);
            *(__half2*)(g_Whh + (size_t)(gr + 8) * NCOLS + col) =
                __floats2half2_rn(acc[mt][nt][2], acc[mt][nt][3]);
#pragma unroll
            for (int cc = 0; cc < 2; cc++) {
                float as = a_sm[coll + cc], ad = a_sm[64 + coll + cc];
                sp[mt][0] = fmaf(acc[mt][nt][cc],     as, sp[mt][0]);
                sp[mt][1] = fmaf(acc[mt][nt][2 + cc], as, sp[mt][1]);
                dp[mt][0] = fmaf(acc[mt][nt][cc],     ad, dp[mt][0]);
                dp[mt][1] = fmaf(acc[mt][nt][2 + cc], ad, dp[mt][1]);
            }
        }
    }
#pragma unroll
    for (int o = 1; o < 4; o <<= 1) {
#pragma unroll
        for (int mt = 0; mt < 2; mt++) {
#pragma unroll
            for (int hf = 0; hf < 2; hf++) {
                sp[mt][hf] += __shfl_xor_sync(0xffffffffu, sp[mt][hf], o);
                dp[mt][hf] += __shfl_xor_sync(0xffffffffu, dp[mt][hf], o);
            }
        }
    }
    if (tig == 0) {
#pragma unroll
        for (int mt = 0; mt < 2; mt++)
#pragma unroll
            for (int hf = 0; hf < 2; hf++) {
                int row = wm * 32 + mt * 16 + gid + hf * 8;   // 0..127
                sd_sm[row * 4 + wn * 2 + 0] = sp[mt][hf];
                sd_sm[row * 4 + wn * 2 + 1] = dp[mt][hf];
            }
    }
    __syncthreads();
    if (tid < 128) {
        float s = sd_sm[tid * 4 + 0] + sd_sm[tid * 4 + 2];
        float d = sd_sm[tid * 4 + 1] + sd_sm[tid * 4 + 3];
        int gr = m0 + tid;
        g_SAB[gr * 8 + h] = make_float4(s, expf(s), expf(0.2f * s), 0.f);
        g_DJE[gr * 8 + h] = make_float4(d, expf(d), expf(0.2f * d), 0.f);
    }
}

// ---------------------------------------------------------------------------
// Kernel 3: aggregation. 1 block/row, 128 threads, fp16 gathers (8B/thread).
// ---------------------------------------------------------------------------
__global__ __launch_bounds__(128) void attn_kernel(float* __restrict__ out)
{
    __shared__ int    s_list[CAP];
    __shared__ float  s_w[CAP * 8];
    __shared__ float4 s_sab[8];

    const int i   = blockIdx.x;
    const int tid = threadIdx.x;
    const int h   = tid >> 4;

    const int nn = g_deg[i];
    if (tid < 8) s_sab[tid] = g_SAB[i * 8 + tid];
    for (int p = tid; p < nn; p += 128) s_list[p] = g_nbr[(size_t)i * CAP + p];
    __syncthreads();

    for (int idx = tid; idx < nn * 8; idx += 128) {
        int q = idx >> 3, hh = idx & 7;
        int j = s_list[q];
        float4 dje = g_DJE[j * 8 + hh];
        float4 sab = s_sab[hh];
        float t = sab.x + dje.x;
        s_w[idx] = (t > 0.f) ? sab.y * dje.y : sab.z * dje.z;
    }
    __syncthreads();

    const float* wp = s_w + h;
    float4 acc = make_float4(0.f, 0.f, 0.f, 0.f);
    float  den = 0.f;

#pragma unroll 4
    for (int q = 0; q < nn; q++) {
        float w = wp[q * 8];
        int   j = s_list[q];
        uint2 v2 = __ldg((const uint2*)(g_Whh + ((size_t)j << 9)) + tid);
        float2 f0 = __half22float2(*(__half2*)&v2.x);
        float2 f1 = __half22float2(*(__half2*)&v2.y);
        acc.x = fmaf(w, f0.x, acc.x);
        acc.y = fmaf(w, f0.y, acc.y);
        acc.z = fmaf(w, f1.x, acc.z);
        acc.w = fmaf(w, f1.y, acc.w);
        den += w;
    }

    float inv = 1.f / den;
    float4 r = make_float4(acc.x * inv, acc.y * inv, acc.z * inv, acc.w * inv);
    r.x = (r.x > 0.f) ? r.x : (expf(r.x) - 1.f);
    r.y = (r.y > 0.f) ? r.y : (expf(r.y) - 1.f);
    r.z = (r.z > 0.f) ? r.z : (expf(r.z) - 1.f);
    r.w = (r.w > 0.f) ? r.w : (expf(r.w) - 1.f);
    *(float4*)(out + (size_t)i * NCOLS + tid * 4) = r;
}

// ---------------------------------------------------------------------------
extern "C" void kernel_launch(void* const* d_in, const int* in_sizes, int n_in,
                              void* d_out, int out_size)
{
    const float* x   = (const float*)d_in[0];   // [4096, 512]
    const float* adj = (const float*)d_in[1];   // [4096, 4096]
    const float* W   = (const float*)d_in[2];   // [8, 512, 64]
    const float* a   = (const float*)d_in[3];   // [8, 128]
    float* out = (float*)d_out;                 // [4096, 512]

    static bool attr_set = false;
    if (!attr_set) {
        cudaFuncSetAttribute(gemm_f16, cudaFuncAttributeMaxDynamicSharedMemorySize, DYN_BYTES);
        attr_set = true;
    }

    prep_x<<<1024, 256>>>(x);
    prep_w<<<256, 256>>>(W);
    scan_kernel<<<N_NODES, 256>>>(adj);
    gemm_f16<<<dim3(NHEADS, N_NODES / 128), 256, DYN_BYTES>>>(a);
    attn_kernel<<<N_NODES, 128>>>(out);
}

// round 14
// speedup vs baseline: 1.3431x; 1.1268x over previous
#include <cuda_runtime.h>
#include <cuda_fp16.h>
#include <cstdint>

// ---------------------------------------------------------------------------
// GAT: N=4096, F_IN=512, HID=64, H=8, alpha=0.2
//  out[n, h*64+d] = elu( softmax_j(leakyrelu(s[h,n]+d[h,j]), mask=adj) @ Wh )
// exp(leakyrelu(s+d)) factorizes -> no per-edge exp.  adj 1% dense -> CSR.
// GEMM: pure fp16 1-term mma.sync.m16n8k16 (legacy HMMA pipe is throughput-
// bound: measured ~13.2us per term-pass regardless of occupancy/grid, so
// term count is the only lever). fp32 accumulate; s/d fused in epilogue.
// Wh stored fp16. Adjacency scan overlapped with GEMM on a second stream.
// ---------------------------------------------------------------------------

#define N_NODES 4096
#define F_IN    512
#define HID     64
#define NHEADS  8
#define NCOLS   512
#define CAP     192

__device__ __half  g_Whh[N_NODES * NCOLS];     // Wh fp16 [N][H*64]
__device__ float4  g_SAB[N_NODES * NHEADS];    // [i*8+h] = (s, e^s, e^.2s, 0)
__device__ float4  g_DJE[N_NODES * NHEADS];
__device__ int     g_deg[N_NODES];
__device__ int     g_nbr[N_NODES * CAP];
__device__ __half  g_xh[N_NODES * F_IN];       // x fp16
__device__ __half  g_Wth[NHEADS * HID * F_IN]; // W^T fp16: [h][n][k]

// ---------------------------------------------------------------------------
// Kernel 0a: x -> fp16
// ---------------------------------------------------------------------------
__global__ __launch_bounds__(256) void prep_x(const float* __restrict__ x)
{
    size_t base = ((size_t)blockIdx.x * 256 + threadIdx.x) * 8;
    float4 p = *(const float4*)(x + base);
    float4 q = *(const float4*)(x + base + 4);
    __align__(16) __half hs[8];
    hs[0] = __float2half_rn(p.x); hs[1] = __float2half_rn(p.y);
    hs[2] = __float2half_rn(p.z); hs[3] = __float2half_rn(p.w);
    hs[4] = __float2half_rn(q.x); hs[5] = __float2half_rn(q.y);
    hs[6] = __float2half_rn(q.z); hs[7] = __float2half_rn(q.w);
    *(uint4*)(g_xh + base) = *(uint4*)hs;
}

// ---------------------------------------------------------------------------
// Kernel 0b: W transpose -> fp16: g_Wth[h][n][k] = fp16(W[h][k][n])
// ---------------------------------------------------------------------------
__global__ __launch_bounds__(256) void prep_w(const float* __restrict__ W)
{
    int b  = blockIdx.x * 256 + threadIdx.x;   // 0..65535
    int k4 = (b & 127) * 4;
    int n  = (b >> 7) & 63;
    int h  = b >> 13;
    const float* src = W + (size_t)h * 32768 + (size_t)k4 * 64 + n;
    __align__(8) __half hs[4];
    hs[0] = __float2half_rn(src[0]);
    hs[1] = __float2half_rn(src[64]);
    hs[2] = __float2half_rn(src[128]);
    hs[3] = __float2half_rn(src[192]);
    *(uint2*)(g_Wth + (size_t)h * 32768 + (size_t)n * 512 + k4) = *(uint2*)hs;
}

// ---------------------------------------------------------------------------
// Kernel 1: adjacency row scan -> CSR (deterministic ascending order)
// ---------------------------------------------------------------------------
__global__ __launch_bounds__(256) void scan_kernel(const float* __restrict__ adj)
{
    __shared__ int wsum[8];
    const int i   = blockIdx.x;
    const int tid = threadIdx.x;
    const int lane = tid & 31, wid = tid >> 5;

    const float4* row = (const float4*)(adj + (size_t)i * N_NODES) + tid * 4;
    unsigned bits = 0;
#pragma unroll
    for (int p = 0; p < 4; p++) {
        float4 v = row[p];
        if (v.x > 0.f) bits |= 1u << (p * 4 + 0);
        if (v.y > 0.f) bits |= 1u << (p * 4 + 1);
        if (v.z > 0.f) bits |= 1u << (p * 4 + 2);
        if (v.w > 0.f) bits |= 1u << (p * 4 + 3);
    }
    int cnt = __popc(bits);
    int incl = cnt;
#pragma unroll
    for (int o = 1; o < 32; o <<= 1) {
        int t = __shfl_up_sync(0xffffffffu, incl, o);
        if (lane >= o) incl += t;
    }
    if (lane == 31) wsum[wid] = incl;
    __syncthreads();
    int wbase = 0;
#pragma unroll
    for (int w = 0; w < 8; w++) if (w < wid) wbase += wsum[w];
    int pos = wbase + incl - cnt;
    if (tid == 0) {
        int t = 0;
#pragma unroll
        for (int w = 0; w < 8; w++) t += wsum[w];
        g_deg[i] = t;
    }
    int base = tid * 16;
    int* dst = g_nbr + (size_t)i * CAP;
    while (bits) {
        int b = __ffs(bits) - 1;
        bits &= bits - 1;
        dst[pos++] = base + b;
    }
}

// ---------------------------------------------------------------------------
// Kernel 2: fp16 1-term GEMM + fused s/d epilogue.
// Block: M=128 x N=64 (one head), BK=32, 256 threads, grid 256.
// 8 warps: wm = warp>>1 (4 x m32), wn = warp&1 (2 x n32 = 4 x n8).
// cp.async double-buffered. Smem row stride 40 halfs -> conflict-free.
// ---------------------------------------------------------------------------
#define NKB   16
#define LDH   40
#define A_H   (128 * LDH)                 // 5120 halfs
#define B_H   (64 * LDH)                  // 2560 halfs
#define BUF_H (A_H + B_H)                 // 7680 halfs per buffer
#define DYN_BYTES (2 * BUF_H * 2 + 512 + 2048)

__device__ __forceinline__ uint32_t smem_u32(const void* p) {
    uint32_t a;
    asm("{ .reg .u64 t; cvta.to.shared.u64 t, %1; cvt.u32.u64 %0, t; }"
        : "=r"(a) : "l"(p));
    return a;
}
__device__ __forceinline__ void cp16(uint32_t dst, const void* src) {
    asm volatile("cp.async.ca.shared.global [%0], [%1], 16;"
                 :: "r"(dst), "l"(src) : "memory");
}
__device__ __forceinline__ void mma_f16(float* d, uint32_t a0, uint32_t a1,
                                        uint32_t a2, uint32_t a3,
                                        uint32_t b0, uint32_t b1)
{
    asm volatile(
        "mma.sync.aligned.m16n8k16.row.col.f32.f16.f16.f32 "
        "{%0,%1,%2,%3}, {%4,%5,%6,%7}, {%8,%9}, {%0,%1,%2,%3};"
        : "+f"(d[0]), "+f"(d[1]), "+f"(d[2]), "+f"(d[3])
        : "r"(a0), "r"(a1), "r"(a2), "r"(a3), "r"(b0), "r"(b1));
}

__global__ __launch_bounds__(256) void gemm_f16(const float* __restrict__ a_g)
{
    extern __shared__ __align__(16) char sm[];
    __half* tiles = (__half*)sm;                        // 2 buffers
    float*  a_sm  = (float*)(sm + 2 * BUF_H * 2);       // 128 floats
    float*  sd_sm = (float*)(sm + 2 * BUF_H * 2 + 512); // [128][2][2]

    const int tid  = threadIdx.x;
    const int lane = tid & 31, warp = tid >> 5;
    const int h    = blockIdx.x;
    const int m0   = blockIdx.y * 128;
    const int wm   = warp >> 1, wn = warp & 1;
    const int gid  = lane >> 2, tig = lane & 3;

    const __half* xh  = g_xh + (size_t)m0 * F_IN;
    const __half* wth = g_Wth + (size_t)h * 32768;

    if (tid < 128) a_sm[tid] = a_g[h * 128 + tid];

    const uint32_t tiles_u = smem_u32(tiles);

    // stage one k-block (id = p*256+tid, p<3): A, B via 16B cp.async
    auto stage = [&](int buf, int k0) {
        uint32_t bu = tiles_u + buf * (BUF_H * 2);
#pragma unroll
        for (int p = 0; p < 3; p++) {
            int id = tid + p * 256;
            if (id < 512) {                       // A: 128 rows x 4 segs
                int r = id >> 2, seg = id & 3;
                cp16(bu + (r * LDH + seg * 8) * 2, xh + (size_t)r * F_IN + k0 + seg * 8);
            } else {                              // B: 64 rows x 4 segs
                int q = id - 512, r = q >> 2, seg = q & 3;
                cp16(bu + (A_H + r * LDH + seg * 8) * 2, wth + (size_t)r * F_IN + k0 + seg * 8);
            }
        }
        asm volatile("cp.async.commit_group;" ::: "memory");
    };

    float acc[2][4][4];
#pragma unroll
    for (int mt = 0; mt < 2; mt++)
#pragma unroll
        for (int nt = 0; nt < 4; nt++)
#pragma unroll
            for (int r = 0; r < 4; r++) acc[mt][nt][r] = 0.f;

    stage(0, 0);

    for (int kb = 0; kb < NKB; kb++) {
        asm volatile("cp.async.wait_group 0;" ::: "memory");
        __syncthreads();
        if (kb + 1 < NKB) stage((kb + 1) & 1, (kb + 1) * 32);

        const __half* Ah = tiles + (kb & 1) * BUF_H;
        const __half* Bh = Ah + A_H;

#pragma unroll
        for (int c = 0; c < 2; c++) {
            const int kb16 = c * 16 + 2 * tig;
            uint32_t bfr[4][2];
#pragma unroll
            for (int nt = 0; nt < 4; nt++) {
                const int col = wn * 32 + nt * 8 + gid;
                bfr[nt][0] = *(const uint32_t*)(Bh + col * LDH + kb16);
                bfr[nt][1] = *(const uint32_t*)(Bh + col * LDH + kb16 + 8);
            }
#pragma unroll
            for (int mt = 0; mt < 2; mt++) {
                const int r0 = wm * 32 + mt * 16 + gid;
                uint32_t ah0 = *(const uint32_t*)(Ah + r0 * LDH + kb16);
                uint32_t ah1 = *(const uint32_t*)(Ah + (r0 + 8) * LDH + kb16);
                uint32_t ah2 = *(const uint32_t*)(Ah + r0 * LDH + kb16 + 8);
                uint32_t ah3 = *(const uint32_t*)(Ah + (r0 + 8) * LDH + kb16 + 8);
#pragma unroll
                for (int nt = 0; nt < 4; nt++)
                    mma_f16(acc[mt][nt], ah0, ah1, ah2, ah3, bfr[nt][0], bfr[nt][1]);
            }
        }
    }

    // ---- epilogue: Wh (fp16) + fused s/d from fp32 accumulators ----
    float sp[2][2], dp[2][2];
#pragma unroll
    for (int mt = 0; mt < 2; mt++) {
        sp[mt][0] = sp[mt][1] = dp[mt][0] = dp[mt][1] = 0.f;
        const int gr = m0 + wm * 32 + mt * 16 + gid;
#pragma unroll
        for (int nt = 0; nt < 4; nt++) {
            const int coll = wn * 32 + nt * 8 + 2 * tig;   // local col 0..63
            const int col  = h * HID + coll;
            *(__half2*)(g_Whh + (size_t)gr * NCOLS + col) =
                __floats2half2_rn(acc[mt][nt][0], acc[mt][nt][1]);
            *(__half2*)(g_Whh + (size_t)(gr + 8) * NCOLS + col) =
                __floats2half2_rn(acc[mt][nt][2], acc[mt][nt][3]);
#pragma unroll
            for (int cc = 0; cc < 2; cc++) {
                float as = a_sm[coll + cc], ad = a_sm[64 + coll + cc];
                sp[mt][0] = fmaf(acc[mt][nt][cc],     as, sp[mt][0]);
                sp[mt][1] = fmaf(acc[mt][nt][2 + cc], as, sp[mt][1]);
                dp[mt][0] = fmaf(acc[mt][nt][cc],     ad, dp[mt][0]);
                dp[mt][1] = fmaf(acc[mt][nt][2 + cc], ad, dp[mt][1]);
            }
        }
    }
#pragma unroll
    for (int o = 1; o < 4; o <<= 1) {
#pragma unroll
        for (int mt = 0; mt < 2; mt++) {
#pragma unroll
            for (int hf = 0; hf < 2; hf++) {
                sp[mt][hf] += __shfl_xor_sync(0xffffffffu, sp[mt][hf], o);
                dp[mt][hf] += __shfl_xor_sync(0xffffffffu, dp[mt][hf], o);
            }
        }
    }
    if (tig == 0) {
#pragma unroll
        for (int mt = 0; mt < 2; mt++)
#pragma unroll
            for (int hf = 0; hf < 2; hf++) {
                int row = wm * 32 + mt * 16 + gid + hf * 8;   // 0..127
                sd_sm[row * 4 + wn * 2 + 0] = sp[mt][hf];
                sd_sm[row * 4 + wn * 2 + 1] = dp[mt][hf];
            }
    }
    __syncthreads();
    if (tid < 128) {
        float s = sd_sm[tid * 4 + 0] + sd_sm[tid * 4 + 2];
        float d = sd_sm[tid * 4 + 1] + sd_sm[tid * 4 + 3];
        int gr = m0 + tid;
        g_SAB[gr * 8 + h] = make_float4(s, expf(s), expf(0.2f * s), 0.f);
        g_DJE[gr * 8 + h] = make_float4(d, expf(d), expf(0.2f * d), 0.f);
    }
}

// ---------------------------------------------------------------------------
// Kernel 3: aggregation. 1 block/row, 128 threads, fp16 gathers (8B/thread).
// ---------------------------------------------------------------------------
__global__ __launch_bounds__(128) void attn_kernel(float* __restrict__ out)
{
    __shared__ int    s_list[CAP];
    __shared__ float  s_w[CAP * 8];
    __shared__ float4 s_sab[8];

    const int i   = blockIdx.x;
    const int tid = threadIdx.x;
    const int h   = tid >> 4;

    const int nn = g_deg[i];
    if (tid < 8) s_sab[tid] = g_SAB[i * 8 + tid];
    for (int p = tid; p < nn; p += 128) s_list[p] = g_nbr[(size_t)i * CAP + p];
    __syncthreads();

    for (int idx = tid; idx < nn * 8; idx += 128) {
        int q = idx >> 3, hh = idx & 7;
        int j = s_list[q];
        float4 dje = g_DJE[j * 8 + hh];
        float4 sab = s_sab[hh];
        float t = sab.x + dje.x;
        s_w[idx] = (t > 0.f) ? sab.y * dje.y : sab.z * dje.z;
    }
    __syncthreads();

    const float* wp = s_w + h;
    float4 acc = make_float4(0.f, 0.f, 0.f, 0.f);
    float  den = 0.f;

#pragma unroll 4
    for (int q = 0; q < nn; q++) {
        float w = wp[q * 8];
        int   j = s_list[q];
        uint2 v2 = __ldg((const uint2*)(g_Whh + ((size_t)j << 9)) + tid);
        float2 f0 = __half22float2(*(__half2*)&v2.x);
        float2 f1 = __half22float2(*(__half2*)&v2.y);
        acc.x = fmaf(w, f0.x, acc.x);
        acc.y = fmaf(w, f0.y, acc.y);
        acc.z = fmaf(w, f1.x, acc.z);
        acc.w = fmaf(w, f1.y, acc.w);
        den += w;
    }

    float inv = 1.f / den;
    float4 r = make_float4(acc.x * inv, acc.y * inv, acc.z * inv, acc.w * inv);
    r.x = (r.x > 0.f) ? r.x : (expf(r.x) - 1.f);
    r.y = (r.y > 0.f) ? r.y : (expf(r.y) - 1.f);
    r.z = (r.z > 0.f) ? r.z : (expf(r.z) - 1.f);
    r.w = (r.w > 0.f) ? r.w : (expf(r.w) - 1.f);
    *(float4*)(out + (size_t)i * NCOLS + tid * 4) = r;
}

// ---------------------------------------------------------------------------
extern "C" void kernel_launch(void* const* d_in, const int* in_sizes, int n_in,
                              void* d_out, int out_size)
{
    const float* x   = (const float*)d_in[0];   // [4096, 512]
    const float* adj = (const float*)d_in[1];   // [4096, 4096]
    const float* W   = (const float*)d_in[2];   // [8, 512, 64]
    const float* a   = (const float*)d_in[3];   // [8, 128]
    float* out = (float*)d_out;                 // [4096, 512]

    static cudaStream_t s2 = nullptr;
    static cudaEvent_t  e1 = nullptr, e2 = nullptr;
    if (!s2) {
        cudaStreamCreateWithFlags(&s2, cudaStreamNonBlocking);
        cudaEventCreateWithFlags(&e1, cudaEventDisableTiming);
        cudaEventCreateWithFlags(&e2, cudaEventDisableTiming);
        cudaFuncSetAttribute(gemm_f16, cudaFuncAttributeMaxDynamicSharedMemorySize, DYN_BYTES);
    }

    // fork: scan (DRAM-bound) runs on s2 concurrently with preps+gemm
    cudaEventRecord(e1, 0);
    cudaStreamWaitEvent(s2, e1, 0);
    scan_kernel<<<N_NODES, 256, 0, s2>>>(adj);
    cudaEventRecord(e2, s2);

    prep_x<<<1024, 256>>>(x);
    prep_w<<<256, 256>>>(W);
    gemm_f16<<<dim3(NHEADS, N_NODES / 128), 256, DYN_BYTES>>>(a);

    // join: attn needs both CSR (s2) and Wh/SAB/DJE (stream 0)
    cudaStreamWaitEvent(0, e2, 0);
    attn_kernel<<<N_NODES, 128>>>(out);
}

// round 15
// speedup vs baseline: 1.4353x; 1.0686x over previous
#include <cuda_runtime.h>
#include <cuda_fp16.h>
#include <cstdint>

// ---------------------------------------------------------------------------
// GAT: N=4096, F_IN=512, HID=64, H=8, alpha=0.2
//  out[n, h*64+d] = elu( softmax_j(leakyrelu(s[h,n]+d[h,j]), mask=adj) @ Wh )
// exp(leakyrelu(s+d)) factorizes -> no per-edge exp.  adj 1% dense -> CSR.
// GEMM: fp16 1-term mma.sync.m16n8k16, BK=64, cp.async double-buffered.
// Wh stored fp16. s/d fused into GEMM epilogue. Scan overlapped on stream 2.
// attn: 4 nodes/block, 64 threads x LDG.128 per node gather.
// ---------------------------------------------------------------------------

#define N_NODES 4096
#define F_IN    512
#define HID     64
#define NHEADS  8
#define NCOLS   512
#define CAP     192

__device__ __half  g_Whh[N_NODES * NCOLS];     // Wh fp16 [N][H*64]
__device__ float4  g_SAB[N_NODES * NHEADS];    // [i*8+h] = (s, e^s, e^.2s, 0)
__device__ float4  g_DJE[N_NODES * NHEADS];
__device__ int     g_deg[N_NODES];
__device__ int     g_nbr[N_NODES * CAP];
__device__ __half  g_xh[N_NODES * F_IN];       // x fp16
__device__ __half  g_Wth[NHEADS * HID * F_IN]; // W^T fp16: [h][n][k]

// ---------------------------------------------------------------------------
// Kernel 0a: x -> fp16
// ---------------------------------------------------------------------------
__global__ __launch_bounds__(256) void prep_x(const float* __restrict__ x)
{
    size_t base = ((size_t)blockIdx.x * 256 + threadIdx.x) * 8;
    float4 p = *(const float4*)(x + base);
    float4 q = *(const float4*)(x + base + 4);
    __align__(16) __half hs[8];
    hs[0] = __float2half_rn(p.x); hs[1] = __float2half_rn(p.y);
    hs[2] = __float2half_rn(p.z); hs[3] = __float2half_rn(p.w);
    hs[4] = __float2half_rn(q.x); hs[5] = __float2half_rn(q.y);
    hs[6] = __float2half_rn(q.z); hs[7] = __float2half_rn(q.w);
    *(uint4*)(g_xh + base) = *(uint4*)hs;
}

// ---------------------------------------------------------------------------
// Kernel 0b: W transpose -> fp16: g_Wth[h][n][k] = fp16(W[h][k][n])
// ---------------------------------------------------------------------------
__global__ __launch_bounds__(256) void prep_w(const float* __restrict__ W)
{
    int b  = blockIdx.x * 256 + threadIdx.x;   // 0..65535
    int k4 = (b & 127) * 4;
    int n  = (b >> 7) & 63;
    int h  = b >> 13;
    const float* src = W + (size_t)h * 32768 + (size_t)k4 * 64 + n;
    __align__(8) __half hs[4];
    hs[0] = __float2half_rn(src[0]);
    hs[1] = __float2half_rn(src[64]);
    hs[2] = __float2half_rn(src[128]);
    hs[3] = __float2half_rn(src[192]);
    *(uint2*)(g_Wth + (size_t)h * 32768 + (size_t)n * 512 + k4) = *(uint2*)hs;
}

// ---------------------------------------------------------------------------
// Kernel 1: adjacency row scan -> CSR (deterministic ascending order)
// ---------------------------------------------------------------------------
__global__ __launch_bounds__(256) void scan_kernel(const float* __restrict__ adj)
{
    __shared__ int wsum[8];
    const int i   = blockIdx.x;
    const int tid = threadIdx.x;
    const int lane = tid & 31, wid = tid >> 5;

    const float4* row = (const float4*)(adj + (size_t)i * N_NODES) + tid * 4;
    unsigned bits = 0;
#pragma unroll
    for (int p = 0; p < 4; p++) {
        float4 v = row[p];
        if (v.x > 0.f) bits |= 1u << (p * 4 + 0);
        if (v.y > 0.f) bits |= 1u << (p * 4 + 1);
        if (v.z > 0.f) bits |= 1u << (p * 4 + 2);
        if (v.w > 0.f) bits |= 1u << (p * 4 + 3);
    }
    int cnt = __popc(bits);
    int incl = cnt;
#pragma unroll
    for (int o = 1; o < 32; o <<= 1) {
        int t = __shfl_up_sync(0xffffffffu, incl, o);
        if (lane >= o) incl += t;
    }
    if (lane == 31) wsum[wid] = incl;
    __syncthreads();
    int wbase = 0;
#pragma unroll
    for (int w = 0; w < 8; w++) if (w < wid) wbase += wsum[w];
    int pos = wbase + incl - cnt;
    if (tid == 0) {
        int t = 0;
#pragma unroll
        for (int w = 0; w < 8; w++) t += wsum[w];
        g_deg[i] = t;
    }
    int base = tid * 16;
    int* dst = g_nbr + (size_t)i * CAP;
    while (bits) {
        int b = __ffs(bits) - 1;
        bits &= bits - 1;
        dst[pos++] = base + b;
    }
}

// ---------------------------------------------------------------------------
// Kernel 2: fp16 1-term GEMM + fused s/d epilogue.
// Block: M=128 x N=64 (one head), BK=64, 256 threads, grid 256, 8 mainloop its.
// 8 warps: wm = warp>>1 (4 x m32), wn = warp&1 (2 x n32 = 4 x n8).
// cp.async double-buffered. Smem row stride 72 halfs -> conflict-free.
// ---------------------------------------------------------------------------
#define NKB   8
#define KBSZ  64
#define LDH   72
#define A_H   (128 * LDH)                 // 9216 halfs
#define B_H   (64 * LDH)                  // 4608 halfs
#define BUF_H (A_H + B_H)                 // 13824 halfs per buffer
#define DYN_BYTES (2 * BUF_H * 2 + 512 + 2048)

__device__ __forceinline__ uint32_t smem_u32(const void* p) {
    uint32_t a;
    asm("{ .reg .u64 t; cvta.to.shared.u64 t, %1; cvt.u32.u64 %0, t; }"
        : "=r"(a) : "l"(p));
    return a;
}
__device__ __forceinline__ void cp16(uint32_t dst, const void* src) {
    asm volatile("cp.async.ca.shared.global [%0], [%1], 16;"
                 :: "r"(dst), "l"(src) : "memory");
}
__device__ __forceinline__ void mma_f16(float* d, uint32_t a0, uint32_t a1,
                                        uint32_t a2, uint32_t a3,
                                        uint32_t b0, uint32_t b1)
{
    asm volatile(
        "mma.sync.aligned.m16n8k16.row.col.f32.f16.f16.f32 "
        "{%0,%1,%2,%3}, {%4,%5,%6,%7}, {%8,%9}, {%0,%1,%2,%3};"
        : "+f"(d[0]), "+f"(d[1]), "+f"(d[2]), "+f"(d[3])
        : "r"(a0), "r"(a1), "r"(a2), "r"(a3), "r"(b0), "r"(b1));
}

__global__ __launch_bounds__(256) void gemm_f16(const float* __restrict__ a_g)
{
    extern __shared__ __align__(16) char sm[];
    __half* tiles = (__half*)sm;                        // 2 buffers
    float*  a_sm  = (float*)(sm + 2 * BUF_H * 2);       // 128 floats
    float*  sd_sm = (float*)(sm + 2 * BUF_H * 2 + 512); // [128][2][2]

    const int tid  = threadIdx.x;
    const int lane = tid & 31, warp = tid >> 5;
    const int h    = blockIdx.x;
    const int m0   = blockIdx.y * 128;
    const int wm   = warp >> 1, wn = warp & 1;
    const int gid  = lane >> 2, tig = lane & 3;

    const __half* xh  = g_xh + (size_t)m0 * F_IN;
    const __half* wth = g_Wth + (size_t)h * 32768;

    if (tid < 128) a_sm[tid] = a_g[h * 128 + tid];

    const uint32_t tiles_u = smem_u32(tiles);

    // stage one 64-k block: A 128x8 segs + B 64x8 segs = 1536 x 16B cp.async
    auto stage = [&](int buf, int k0) {
        uint32_t bu = tiles_u + buf * (BUF_H * 2);
#pragma unroll
        for (int p = 0; p < 6; p++) {
            int id = tid + p * 256;
            if (id < 1024) {                      // A: 128 rows x 8 segs
                int r = id >> 3, seg = id & 7;
                cp16(bu + (r * LDH + seg * 8) * 2, xh + (size_t)r * F_IN + k0 + seg * 8);
            } else {                              // B: 64 rows x 8 segs
                int q = id - 1024, r = q >> 3, seg = q & 7;
                cp16(bu + (A_H + r * LDH + seg * 8) * 2, wth + (size_t)r * F_IN + k0 + seg * 8);
            }
        }
        asm volatile("cp.async.commit_group;" ::: "memory");
    };

    float acc[2][4][4];
#pragma unroll
    for (int mt = 0; mt < 2; mt++)
#pragma unroll
        for (int nt = 0; nt < 4; nt++)
#pragma unroll
            for (int r = 0; r < 4; r++) acc[mt][nt][r] = 0.f;

    stage(0, 0);

    for (int kb = 0; kb < NKB; kb++) {
        asm volatile("cp.async.wait_group 0;" ::: "memory");
        __syncthreads();
        if (kb + 1 < NKB) stage((kb + 1) & 1, (kb + 1) * KBSZ);

        const __half* Ah = tiles + (kb & 1) * BUF_H;
        const __half* Bh = Ah + A_H;

#pragma unroll
        for (int c = 0; c < 4; c++) {
            const int kb16 = c * 16 + 2 * tig;
            uint32_t bfr[4][2];
#pragma unroll
            for (int nt = 0; nt < 4; nt++) {
                const int col = wn * 32 + nt * 8 + gid;
                bfr[nt][0] = *(const uint32_t*)(Bh + col * LDH + kb16);
                bfr[nt][1] = *(const uint32_t*)(Bh + col * LDH + kb16 + 8);
            }
#pragma unroll
            for (int mt = 0; mt < 2; mt++) {
                const int r0 = wm * 32 + mt * 16 + gid;
                uint32_t ah0 = *(const uint32_t*)(Ah + r0 * LDH + kb16);
                uint32_t ah1 = *(const uint32_t*)(Ah + (r0 + 8) * LDH + kb16);
                uint32_t ah2 = *(const uint32_t*)(Ah + r0 * LDH + kb16 + 8);
                uint32_t ah3 = *(const uint32_t*)(Ah + (r0 + 8) * LDH + kb16 + 8);
#pragma unroll
                for (int nt = 0; nt < 4; nt++)
                    mma_f16(acc[mt][nt], ah0, ah1, ah2, ah3, bfr[nt][0], bfr[nt][1]);
            }
        }
    }

    // ---- epilogue: Wh (fp16) + fused s/d from fp32 accumulators ----
    float sp[2][2], dp[2][2];
#pragma unroll
    for (int mt = 0; mt < 2; mt++) {
        sp[mt][0] = sp[mt][1] = dp[mt][0] = dp[mt][1] = 0.f;
        const int gr = m0 + wm * 32 + mt * 16 + gid;
#pragma unroll
        for (int nt = 0; nt < 4; nt++) {
            const int coll = wn * 32 + nt * 8 + 2 * tig;   // local col 0..63
            const int col  = h * HID + coll;
            *(__half2*)(g_Whh + (size_t)gr * NCOLS + col) =
                __floats2half2_rn(acc[mt][nt][0], acc[mt][nt][1]);
            *(__half2*)(g_Whh + (size_t)(gr + 8) * NCOLS + col) =
                __floats2half2_rn(acc[mt][nt][2], acc[mt][nt][3]);
#pragma unroll
            for (int cc = 0; cc < 2; cc++) {
                float as = a_sm[coll + cc], ad = a_sm[64 + coll + cc];
                sp[mt][0] = fmaf(acc[mt][nt][cc],     as, sp[mt][0]);
                sp[mt][1] = fmaf(acc[mt][nt][2 + cc], as, sp[mt][1]);
                dp[mt][0] = fmaf(acc[mt][nt][cc],     ad, dp[mt][0]);
                dp[mt][1] = fmaf(acc[mt][nt][2 + cc], ad, dp[mt][1]);
            }
        }
    }
#pragma unroll
    for (int o = 1; o < 4; o <<= 1) {
#pragma unroll
        for (int mt = 0; mt < 2; mt++) {
#pragma unroll
            for (int hf = 0; hf < 2; hf++) {
                sp[mt][hf] += __shfl_xor_sync(0xffffffffu, sp[mt][hf], o);
                dp[mt][hf] += __shfl_xor_sync(0xffffffffu, dp[mt][hf], o);
            }
        }
    }
    if (tig == 0) {
#pragma unroll
        for (int mt = 0; mt < 2; mt++)
#pragma unroll
            for (int hf = 0; hf < 2; hf++) {
                int row = wm * 32 + mt * 16 + gid + hf * 8;   // 0..127
                sd_sm[row * 4 + wn * 2 + 0] = sp[mt][hf];
                sd_sm[row * 4 + wn * 2 + 1] = dp[mt][hf];
            }
    }
    __syncthreads();
    if (tid < 128) {
        float s = sd_sm[tid * 4 + 0] + sd_sm[tid * 4 + 2];
        float d = sd_sm[tid * 4 + 1] + sd_sm[tid * 4 + 3];
        int gr = m0 + tid;
        g_SAB[gr * 8 + h] = make_float4(s, expf(s), expf(0.2f * s), 0.f);
        g_DJE[gr * 8 + h] = make_float4(d, expf(d), expf(0.2f * d), 0.f);
    }
}

// ---------------------------------------------------------------------------
// Kernel 3: aggregation. 4 nodes/block, 256 threads (64/node), LDG.128 gather.
// Thread ln (0..63) of node nd covers halfs [ln*8, ln*8+8) = head ln>>3.
// ---------------------------------------------------------------------------
__global__ __launch_bounds__(256) void attn_kernel(float* __restrict__ out)
{
    __shared__ int    s_list[4][CAP];
    __shared__ float  s_w[4][CAP * 8];
    __shared__ float4 s_sab[4][8];

    const int tid = threadIdx.x;
    const int nd  = tid >> 6;           // node slot 0..3
    const int ln  = tid & 63;           // thread within node
    const int i   = blockIdx.x * 4 + nd;
    const int h   = ln >> 3;            // 8 threads per head

    const int nn = g_deg[i];
    if (ln < 8) s_sab[nd][ln] = g_SAB[i * 8 + ln];
    for (int p = ln; p < nn; p += 64) s_list[nd][p] = g_nbr[(size_t)i * CAP + p];
    __syncthreads();

    for (int idx = ln; idx < nn * 8; idx += 64) {
        int q = idx >> 3, hh = idx & 7;
        int j = s_list[nd][q];
        float4 dje = g_DJE[j * 8 + hh];
        float4 sab = s_sab[nd][hh];
        float t = sab.x + dje.x;
        s_w[nd][idx] = (t > 0.f) ? sab.y * dje.y : sab.z * dje.z;
    }
    __syncthreads();

    const float* wp = s_w[nd] + h;
    const int*   lp = s_list[nd];
    float acc[8];
#pragma unroll
    for (int r = 0; r < 8; r++) acc[r] = 0.f;
    float den = 0.f;

#pragma unroll 4
    for (int q = 0; q < nn; q++) {
        float w = wp[q * 8];
        int   j = lp[q];
        uint4 v = __ldg((const uint4*)(g_Whh + ((size_t)j << 9)) + ln);
        float2 f0 = __half22float2(*(__half2*)&v.x);
        float2 f1 = __half22float2(*(__half2*)&v.y);
        float2 f2 = __half22float2(*(__half2*)&v.z);
        float2 f3 = __half22float2(*(__half2*)&v.w);
        acc[0] = fmaf(w, f0.x, acc[0]); acc[1] = fmaf(w, f0.y, acc[1]);
        acc[2] = fmaf(w, f1.x, acc[2]); acc[3] = fmaf(w, f1.y, acc[3]);
        acc[4] = fmaf(w, f2.x, acc[4]); acc[5] = fmaf(w, f2.y, acc[5]);
        acc[6] = fmaf(w, f3.x, acc[6]); acc[7] = fmaf(w, f3.y, acc[7]);
        den += w;
    }

    float inv = 1.f / den;
    float r[8];
#pragma unroll
    for (int c = 0; c < 8; c++) {
        float t = acc[c] * inv;
        r[c] = (t > 0.f) ? t : (expf(t) - 1.f);
    }
    float* dst = out + (size_t)i * NCOLS + ln * 8;
    *(float4*)(dst)     = make_float4(r[0], r[1], r[2], r[3]);
    *(float4*)(dst + 4) = make_float4(r[4], r[5], r[6], r[7]);
}

// ---------------------------------------------------------------------------
extern "C" void kernel_launch(void* const* d_in, const int* in_sizes, int n_in,
                              void* d_out, int out_size)
{
    const float* x   = (const float*)d_in[0];   // [4096, 512]
    const float* adj = (const float*)d_in[1];   // [4096, 4096]
    const float* W   = (const float*)d_in[2];   // [8, 512, 64]
    const float* a   = (const float*)d_in[3];   // [8, 128]
    float* out = (float*)d_out;                 // [4096, 512]

    static cudaStream_t s2 = nullptr;
    static cudaEvent_t  e1 = nullptr, e2 = nullptr;
    if (!s2) {
        cudaStreamCreateWithFlags(&s2, cudaStreamNonBlocking);
        cudaEventCreateWithFlags(&e1, cudaEventDisableTiming);
        cudaEventCreateWithFlags(&e2, cudaEventDisableTiming);
        cudaFuncSetAttribute(gemm_f16, cudaFuncAttributeMaxDynamicSharedMemorySize, DYN_BYTES);
    }

    // fork: scan (DRAM-bound) runs on s2 concurrently with preps+gemm
    cudaEventRecord(e1, 0);
    cudaStreamWaitEvent(s2, e1, 0);
    scan_kernel<<<N_NODES, 256, 0, s2>>>(adj);
    cudaEventRecord(e2, s2);

    prep_x<<<1024, 256>>>(x);
    prep_w<<<256, 256>>>(W);
    gemm_f16<<<dim3(NHEADS, N_NODES / 128), 256, DYN_BYTES>>>(a);

    // join: attn needs both CSR (s2) and Wh/SAB/DJE (stream 0)
    cudaStreamWaitEvent(0, e2, 0);
    attn_kernel<<<N_NODES / 4, 256>>>(out);
}